// round 13
// baseline (speedup 1.0000x reference)
#include <cuda_runtime.h>
#include <math.h>

#define B_   16
#define T_   512
#define F_   17
#define K_   20
#define FEAT (F_*K_)        // 340
#define FL   30
#define NFR  (T_ - FL + 1)  // 483
#define GF   7              // frames per corr CTA (483 = 69*7 exactly)
#define NGRP (NFR / GF)     // 69
#define ROWS_ST (FL + GF - 1)  // 36 staged rows
#define TB   30
#define NTBLK ((T_ + TB - 1) / TB)   // 18
#define EPSF 1e-12f

// Scratch: ping-pong activation buffers for both towers stacked as 32 "batches".
__device__ float g_bufA[2 * B_ * T_ * F_ * K_];
__device__ float g_bufB[2 * B_ * T_ * F_ * K_];

// Weights/biases in constant memory (warp-uniform -> LDC port, no L1TEX).
__constant__ __align__(16) float CW0[9 * 1  * K_];
__constant__ __align__(16) float CW1[9 * K_ * K_];
__constant__ __align__(16) float CW2[9 * K_ * K_];
__constant__ float CB0[K_];
__constant__ float CB1[K_];
__constant__ float CB2[K_];

// ---------------------------------------------------------------------------
// Conv 3x3 SAME + bias + ReLU — unchanged round-7/11 winner (~82us per layer).
// ---------------------------------------------------------------------------
template<int CIN, bool FIRST, int SRC, int DST, int LAYER>
__global__ void __launch_bounds__(256) conv_kernel(
    const float* __restrict__ in0, const float* __restrict__ in1)
{
    constexpr int CINP = (CIN % 2 == 0) ? CIN + 1 : CIN;

    extern __shared__ float tile[];

    const int tid = threadIdx.x;
    const int t0  = blockIdx.x * TB;
    const int bb  = blockIdx.y;

    const float* src;
    if (FIRST) {
        src = (bb < B_) ? (in0 + (size_t)bb * T_ * F_)
                        : (in1 + (size_t)(bb - B_) * T_ * F_);
    } else {
        const float* base = (SRC == 0) ? g_bufA : g_bufB;
        src = base + (size_t)bb * T_ * F_ * CIN;
    }
    float* dst = ((DST == 0) ? g_bufA : g_bufB);

    const int tileN = (TB + 2) * (F_ + 2) * CIN;
    for (int i = tid; i < tileN; i += 256) {
        int cin  = i % CIN;
        int rest = i / CIN;
        int ff   = rest % (F_ + 2);
        int tt   = rest / (F_ + 2);
        int t = t0 - 1 + tt;
        int f = ff - 1;
        float v = 0.f;
        if (t >= 0 && t < T_ && f >= 0 && f < F_)
            v = src[((size_t)t * F_ + f) * CIN + cin];
        tile[(tt * (F_ + 2) + ff) * CINP + cin] = v;
    }
    __syncthreads();

    float acc0[K_], acc1[K_];
#pragma unroll
    for (int k = 0; k < K_; k++) {
        float bk;
        if constexpr (LAYER == 0) bk = CB0[k];
        else if constexpr (LAYER == 1) bk = CB1[k];
        else bk = CB2[k];
        acc0[k] = bk; acc1[k] = bk;
    }

    const bool ok0 = (tid < TB * F_);
    const bool ok1 = (tid + 256 < TB * F_);
    const int pos0 = ok0 ? tid : 0;
    const int pos1 = ok1 ? (tid + 256) : 0;
    const int lt0 = pos0 / F_, lf0 = pos0 % F_;
    const int lt1 = pos1 / F_, lf1 = pos1 % F_;

    for (int cin = 0; cin < CIN; cin++) {
#pragma unroll
        for (int dt = 0; dt < 3; dt++) {
#pragma unroll
            for (int df = 0; df < 3; df++) {
                const int wbase = ((dt * 3 + df) * CIN + cin) * K_;
                float i0 = tile[((lt0 + dt) * (F_ + 2) + lf0 + df) * CINP + cin];
                float i1 = tile[((lt1 + dt) * (F_ + 2) + lf1 + df) * CINP + cin];
#pragma unroll
                for (int q = 0; q < 5; q++) {
                    float4 wv;
                    if constexpr (LAYER == 0)
                        wv = reinterpret_cast<const float4*>(CW0 + wbase)[q];
                    else if constexpr (LAYER == 1)
                        wv = reinterpret_cast<const float4*>(CW1 + wbase)[q];
                    else
                        wv = reinterpret_cast<const float4*>(CW2 + wbase)[q];
                    acc0[4*q+0] = fmaf(i0, wv.x, acc0[4*q+0]);
                    acc0[4*q+1] = fmaf(i0, wv.y, acc0[4*q+1]);
                    acc0[4*q+2] = fmaf(i0, wv.z, acc0[4*q+2]);
                    acc0[4*q+3] = fmaf(i0, wv.w, acc0[4*q+3]);
                    acc1[4*q+0] = fmaf(i1, wv.x, acc1[4*q+0]);
                    acc1[4*q+1] = fmaf(i1, wv.y, acc1[4*q+1]);
                    acc1[4*q+2] = fmaf(i1, wv.z, acc1[4*q+2]);
                    acc1[4*q+3] = fmaf(i1, wv.w, acc1[4*q+3]);
                }
            }
        }
    }

    if (ok0 && (t0 + lt0) < T_) {
        int t = t0 + lt0;
        float* o = dst + (((size_t)bb * T_ + t) * F_ + lf0) * K_;
#pragma unroll
        for (int k = 0; k < K_; k++) o[k] = fmaxf(acc0[k], 0.f);
    }
    if (ok1 && (t0 + lt1) < T_) {
        int t = t0 + lt1;
        float* o = dst + (((size_t)bb * T_ + t) * F_ + lf1) * K_;
#pragma unroll
        for (int k = 0; k < K_; k++) o[k] = fmaxf(acc1[k], 0.f);
    }
}

// ---------------------------------------------------------------------------
// Grouped per-frame double-normalized cross-correlation.
// One CTA per (frame-group of GF=7, batch): 36 shared rows staged ONCE in
// fp32 smem (global traffic /5.8; corr was L2-BW bound at ~4.3TB/s).
// Stats are recomputed FRESH for every frame (one-pass over 30 rows) --
// NO sliding updates: sliding roundoff residue in S1/S2 exploded on
// constant/dead-ReLU columns (clamped var=0 -> inv=1e12 -> z~1e4).
// Fresh one-pass keeps all-zero windows exact (the R11-validated numerics).
// Phase B normalizes on the fly in fp32 from the coef array.
// ---------------------------------------------------------------------------
__global__ void __launch_bounds__(256) corr_kernel(float* __restrict__ out)
{
    extern __shared__ float sm[];
    float*  rawS = sm;                       // 36*340 fp32
    float*  rawX = sm + ROWS_ST * FEAT;      // 36*340 fp32
    float4* coef = reinterpret_cast<float4*>(sm + 2 * ROWS_ST * FEAT); // 340 float4
    __shared__ float red[8];

    const int grp = blockIdx.x;   // 0..68
    const int b   = blockIdx.y;   // 0..15
    const int tid = threadIdx.x;
    const int fr0 = grp * GF;

    const float* S = g_bufA + ((size_t)b * T_ + fr0) * FEAT;
    const float* X = g_bufA + ((size_t)(b + B_) * T_ + fr0) * FEAT;

    // Stage 36 rows of both towers, fp32, float4 flat copy (rows contiguous;
    // fr0*FEAT = grp*2380 is a multiple of 4 -> 16B aligned).
    {
        const int n4 = ROWS_ST * FEAT / 4;   // 3060
        const float4* S4 = reinterpret_cast<const float4*>(S);
        const float4* X4 = reinterpret_cast<const float4*>(X);
        float4* rS4 = reinterpret_cast<float4*>(rawS);
        float4* rX4 = reinterpret_cast<float4*>(rawX);
        for (int i = tid; i < n4; i += 256) { rS4[i] = S4[i]; rX4[i] = X4[i]; }
    }
    __syncthreads();

    const int warp = tid >> 5, lane = tid & 31;
    float acc = 0.f;

    for (int j = 0; j < GF; j++) {
        if (j > 0) __syncthreads();   // prior Phase B done before coef overwrite

        // Fresh one-pass column stats for frame j (rows j..j+29) -> coef.
#pragma unroll
        for (int slot = 0; slot < 3; slot++) {
            int task = tid + slot * 256;
            if (task < 2 * FEAT) {
                const bool isS = (task < FEAT);
                const int col = isS ? task : task - FEAT;
                const float* base = isS ? rawS : rawX;
                float s = 0.f, s2 = 0.f;
#pragma unroll
                for (int t = 0; t < FL; t++) {
                    float r = base[(j + t) * FEAT + col];
                    s += r; s2 = fmaf(r, r, s2);
                }
                float mu  = s * (1.0f / FL);
                float var = fmaxf(s2 - (float)FL * mu * mu, 0.f);
                float inv = 1.f / (sqrtf(var) + EPSF);
                if (isS) { coef[col].x = mu; coef[col].y = inv; }
                else     { coef[col].z = mu; coef[col].w = inv; }
            }
        }
        __syncthreads();

        // Phase B: one warp per row (8 warps over 30 rows), on-the-fly
        // normalization; row normalization algebraic from 5 warp sums.
        for (int t = warp; t < FL; t += 8) {
            const float* rS = rawS + (j + t) * FEAT;
            const float* rX = rawX + (j + t) * FEAT;
            float aU = 0.f, aV = 0.f, a2U = 0.f, a2V = 0.f, aUV = 0.f;
#pragma unroll
            for (int it = 0; it < 11; it++) {
                int c = it * 32 + lane;
                if (c < FEAT) {
                    float4 cf = coef[c];
                    float u = (rS[c] - cf.x) * cf.y;
                    float v = (rX[c] - cf.z) * cf.w;
                    aU += u; aV += v;
                    a2U = fmaf(u, u, a2U);
                    a2V = fmaf(v, v, a2V);
                    aUV = fmaf(u, v, aUV);
                }
            }
#pragma unroll
            for (int o = 16; o > 0; o >>= 1) {
                aU  += __shfl_down_sync(0xffffffffu, aU,  o);
                aV  += __shfl_down_sync(0xffffffffu, aV,  o);
                a2U += __shfl_down_sync(0xffffffffu, a2U, o);
                a2V += __shfl_down_sync(0xffffffffu, a2V, o);
                aUV += __shfl_down_sync(0xffffffffu, aUV, o);
            }
            if (lane == 0) {
                float muU = aU * (1.0f / FEAT), muV = aV * (1.0f / FEAT);
                float sgU = sqrtf(fmaxf(a2U - (float)FEAT * muU * muU, 0.f));
                float sgV = sqrtf(fmaxf(a2V - (float)FEAT * muV * muV, 0.f));
                float dot = aUV - (float)FEAT * muU * muV;
                acc += dot / ((sgU + EPSF) * (sgV + EPSF));
            }
        }
    }

    if (lane == 0) red[warp] = acc;
    __syncthreads();
    if (tid == 0) {
        float tot = 0.f;
#pragma unroll
        for (int i = 0; i < 8; i++) tot += red[i];
        atomicAdd(&out[b], tot * (1.0f / ((float)FL * (float)NFR)));
    }
}

__global__ void zero_out(float* out, int n)
{
    int i = blockIdx.x * blockDim.x + threadIdx.x;
    if (i < n) out[i] = 0.f;
}

extern "C" void kernel_launch(void* const* d_in, const int* in_sizes, int n_in,
                              void* d_out, int out_size)
{
    const float* s  = (const float*)d_in[0];
    const float* x  = (const float*)d_in[1];
    const float* w0 = (const float*)d_in[2];
    const float* b0 = (const float*)d_in[3];
    const float* w1 = (const float*)d_in[4];
    const float* b1 = (const float*)d_in[5];
    const float* w2 = (const float*)d_in[6];
    const float* b2 = (const float*)d_in[7];
    float* out = (float*)d_out;

    cudaMemcpyToSymbolAsync(CW0, w0, 9 * 1  * K_ * sizeof(float), 0, cudaMemcpyDeviceToDevice, 0);
    cudaMemcpyToSymbolAsync(CB0, b0, K_ * sizeof(float),          0, cudaMemcpyDeviceToDevice, 0);
    cudaMemcpyToSymbolAsync(CW1, w1, 9 * K_ * K_ * sizeof(float), 0, cudaMemcpyDeviceToDevice, 0);
    cudaMemcpyToSymbolAsync(CB1, b1, K_ * sizeof(float),          0, cudaMemcpyDeviceToDevice, 0);
    cudaMemcpyToSymbolAsync(CW2, w2, 9 * K_ * K_ * sizeof(float), 0, cudaMemcpyDeviceToDevice, 0);
    cudaMemcpyToSymbolAsync(CB2, b2, K_ * sizeof(float),          0, cudaMemcpyDeviceToDevice, 0);

    zero_out<<<1, 32>>>(out, out_size);

    const int smem1  = (TB + 2) * (F_ + 2) * 1  * (int)sizeof(float);  //  2432 B
    const int smem20 = (TB + 2) * (F_ + 2) * 21 * (int)sizeof(float);  // 51072 B
    const int smemC  = (2 * ROWS_ST * FEAT) * (int)sizeof(float)
                     + FEAT * (int)sizeof(float4);                     // 103360 B

    cudaFuncSetAttribute(conv_kernel<K_, false, 0, 1, 1>,
                         cudaFuncAttributeMaxDynamicSharedMemorySize, smem20);
    cudaFuncSetAttribute(conv_kernel<K_, false, 1, 0, 2>,
                         cudaFuncAttributeMaxDynamicSharedMemorySize, smem20);
    cudaFuncSetAttribute(corr_kernel,
                         cudaFuncAttributeMaxDynamicSharedMemorySize, smemC);

    dim3 cgrid(NTBLK, 2 * B_);   // 18 x 32 = 576 CTAs
    conv_kernel<1,  true,  0, 0, 0><<<cgrid, 256, smem1 >>>(s, x);             // -> bufA
    conv_kernel<K_, false, 0, 1, 1><<<cgrid, 256, smem20>>>(nullptr, nullptr); // A -> B
    conv_kernel<K_, false, 1, 0, 2><<<cgrid, 256, smem20>>>(nullptr, nullptr); // B -> A

    dim3 ggrid(NGRP, B_);        // 69 x 16 = 1104 CTAs
    corr_kernel<<<ggrid, 256, smemC>>>(out);
}

// round 14
// speedup vs baseline: 1.0263x; 1.0263x over previous
#include <cuda_runtime.h>
#include <math.h>

#define B_   16
#define T_   512
#define F_   17
#define K_   20
#define FEAT (F_*K_)        // 340
#define FL   30
#define NFR  (T_ - FL + 1)  // 483
#define GF   7              // frames per corr CTA (483 = 69*7 exactly)
#define NGRP (NFR / GF)     // 69
#define ROWS_ST (FL + GF - 1)  // 36 staged rows
#define TB   30
#define NTBLK ((T_ + TB - 1) / TB)   // 18
#define EPSF 1e-12f

// Scratch: ping-pong activation buffers for both towers stacked as 32 "batches".
__device__ float g_bufA[2 * B_ * T_ * F_ * K_];
__device__ float g_bufB[2 * B_ * T_ * F_ * K_];

// Weights/biases in constant memory (warp-uniform -> LDC port, no L1TEX).
__constant__ __align__(16) float CW0[9 * 1  * K_];
__constant__ __align__(16) float CW1[9 * K_ * K_];
__constant__ __align__(16) float CW2[9 * K_ * K_];
__constant__ float CB0[K_];
__constant__ float CB1[K_];
__constant__ float CB2[K_];

// ---------------------------------------------------------------------------
// Conv 3x3 SAME + bias + ReLU — unchanged round-7/11/13 winner (~82us/layer).
// ---------------------------------------------------------------------------
template<int CIN, bool FIRST, int SRC, int DST, int LAYER>
__global__ void __launch_bounds__(256) conv_kernel(
    const float* __restrict__ in0, const float* __restrict__ in1)
{
    constexpr int CINP = (CIN % 2 == 0) ? CIN + 1 : CIN;

    extern __shared__ float tile[];

    const int tid = threadIdx.x;
    const int t0  = blockIdx.x * TB;
    const int bb  = blockIdx.y;

    const float* src;
    if (FIRST) {
        src = (bb < B_) ? (in0 + (size_t)bb * T_ * F_)
                        : (in1 + (size_t)(bb - B_) * T_ * F_);
    } else {
        const float* base = (SRC == 0) ? g_bufA : g_bufB;
        src = base + (size_t)bb * T_ * F_ * CIN;
    }
    float* dst = ((DST == 0) ? g_bufA : g_bufB);

    const int tileN = (TB + 2) * (F_ + 2) * CIN;
    for (int i = tid; i < tileN; i += 256) {
        int cin  = i % CIN;
        int rest = i / CIN;
        int ff   = rest % (F_ + 2);
        int tt   = rest / (F_ + 2);
        int t = t0 - 1 + tt;
        int f = ff - 1;
        float v = 0.f;
        if (t >= 0 && t < T_ && f >= 0 && f < F_)
            v = src[((size_t)t * F_ + f) * CIN + cin];
        tile[(tt * (F_ + 2) + ff) * CINP + cin] = v;
    }
    __syncthreads();

    float acc0[K_], acc1[K_];
#pragma unroll
    for (int k = 0; k < K_; k++) {
        float bk;
        if constexpr (LAYER == 0) bk = CB0[k];
        else if constexpr (LAYER == 1) bk = CB1[k];
        else bk = CB2[k];
        acc0[k] = bk; acc1[k] = bk;
    }

    const bool ok0 = (tid < TB * F_);
    const bool ok1 = (tid + 256 < TB * F_);
    const int pos0 = ok0 ? tid : 0;
    const int pos1 = ok1 ? (tid + 256) : 0;
    const int lt0 = pos0 / F_, lf0 = pos0 % F_;
    const int lt1 = pos1 / F_, lf1 = pos1 % F_;

    for (int cin = 0; cin < CIN; cin++) {
#pragma unroll
        for (int dt = 0; dt < 3; dt++) {
#pragma unroll
            for (int df = 0; df < 3; df++) {
                const int wbase = ((dt * 3 + df) * CIN + cin) * K_;
                float i0 = tile[((lt0 + dt) * (F_ + 2) + lf0 + df) * CINP + cin];
                float i1 = tile[((lt1 + dt) * (F_ + 2) + lf1 + df) * CINP + cin];
#pragma unroll
                for (int q = 0; q < 5; q++) {
                    float4 wv;
                    if constexpr (LAYER == 0)
                        wv = reinterpret_cast<const float4*>(CW0 + wbase)[q];
                    else if constexpr (LAYER == 1)
                        wv = reinterpret_cast<const float4*>(CW1 + wbase)[q];
                    else
                        wv = reinterpret_cast<const float4*>(CW2 + wbase)[q];
                    acc0[4*q+0] = fmaf(i0, wv.x, acc0[4*q+0]);
                    acc0[4*q+1] = fmaf(i0, wv.y, acc0[4*q+1]);
                    acc0[4*q+2] = fmaf(i0, wv.z, acc0[4*q+2]);
                    acc0[4*q+3] = fmaf(i0, wv.w, acc0[4*q+3]);
                    acc1[4*q+0] = fmaf(i1, wv.x, acc1[4*q+0]);
                    acc1[4*q+1] = fmaf(i1, wv.y, acc1[4*q+1]);
                    acc1[4*q+2] = fmaf(i1, wv.z, acc1[4*q+2]);
                    acc1[4*q+3] = fmaf(i1, wv.w, acc1[4*q+3]);
                }
            }
        }
    }

    if (ok0 && (t0 + lt0) < T_) {
        int t = t0 + lt0;
        float* o = dst + (((size_t)bb * T_ + t) * F_ + lf0) * K_;
#pragma unroll
        for (int k = 0; k < K_; k++) o[k] = fmaxf(acc0[k], 0.f);
    }
    if (ok1 && (t0 + lt1) < T_) {
        int t = t0 + lt1;
        float* o = dst + (((size_t)bb * T_ + t) * F_ + lf1) * K_;
#pragma unroll
        for (int k = 0; k < K_; k++) o[k] = fmaxf(acc1[k], 0.f);
    }
}

// ---------------------------------------------------------------------------
// Grouped per-frame double-normalized cross-correlation.
// R14 changes vs R13 (structure & numerics otherwise identical):
//   * 512 threads/CTA (32 warps/SM at 2 CTAs) -> latency/barrier bubbles
//     hidden (R13 ran at ~50% of its LDS-bound with 16 warps/SM).
//   * Warp w handles rows (w, w+16) of each frame, sharing ONE coef load
//     per column -> coef LDS bytes halved (was 2/3 of Phase-B traffic).
// Stats stay FRESH one-pass per frame (exact for all-zero windows; the
// sliding variant's clamped-var blowup was the R12 failure).
// ---------------------------------------------------------------------------
__global__ void __launch_bounds__(512, 2) corr_kernel(float* __restrict__ out)
{
    extern __shared__ float sm[];
    float*  rawS = sm;                       // 36*340 fp32
    float*  rawX = sm + ROWS_ST * FEAT;      // 36*340 fp32
    float4* coef = reinterpret_cast<float4*>(sm + 2 * ROWS_ST * FEAT); // 340 float4
    __shared__ float red[16];

    const int grp = blockIdx.x;   // 0..68
    const int b   = blockIdx.y;   // 0..15
    const int tid = threadIdx.x;
    const int fr0 = grp * GF;

    const float* S = g_bufA + ((size_t)b * T_ + fr0) * FEAT;
    const float* X = g_bufA + ((size_t)(b + B_) * T_ + fr0) * FEAT;

    // Stage 36 rows of both towers (rows contiguous; fr0*FEAT multiple of 4).
    {
        const int n4 = ROWS_ST * FEAT / 4;   // 3060
        const float4* S4 = reinterpret_cast<const float4*>(S);
        const float4* X4 = reinterpret_cast<const float4*>(X);
        float4* rS4 = reinterpret_cast<float4*>(rawS);
        float4* rX4 = reinterpret_cast<float4*>(rawX);
        for (int i = tid; i < n4; i += 512) { rS4[i] = S4[i]; rX4[i] = X4[i]; }
    }
    __syncthreads();

    const int warp = tid >> 5, lane = tid & 31;
    float acc = 0.f;

    const int tA = warp;            // rows 0..15
    const int tB = warp + 16;       // rows 16..31 (valid when < FL)
    const bool hasB = (tB < FL);    // warps 0..13

    for (int j = 0; j < GF; j++) {
        if (j > 0) __syncthreads();   // prior Phase B done before coef overwrite

        // Fresh one-pass column stats for frame j (rows j..j+29) -> coef.
#pragma unroll
        for (int slot = 0; slot < 2; slot++) {
            int task = tid + slot * 512;
            if (task < 2 * FEAT) {
                const bool isS = (task < FEAT);
                const int col = isS ? task : task - FEAT;
                const float* base = isS ? rawS : rawX;
                float s = 0.f, s2 = 0.f;
#pragma unroll
                for (int t = 0; t < FL; t++) {
                    float r = base[(j + t) * FEAT + col];
                    s += r; s2 = fmaf(r, r, s2);
                }
                float mu  = s * (1.0f / FL);
                float var = fmaxf(s2 - (float)FL * mu * mu, 0.f);
                float inv = 1.f / (sqrtf(var) + EPSF);
                if (isS) { coef[col].x = mu; coef[col].y = inv; }
                else     { coef[col].z = mu; coef[col].w = inv; }
            }
        }
        __syncthreads();

        // Phase B: warp handles rows tA and (if valid) tB, sharing coef loads.
        {
            const float* rSA = rawS + (j + tA) * FEAT;
            const float* rXA = rawX + (j + tA) * FEAT;
            const float* rSB = rawS + (j + (hasB ? tB : tA)) * FEAT;
            const float* rXB = rawX + (j + (hasB ? tB : tA)) * FEAT;

            float aU1 = 0.f, aV1 = 0.f, a2U1 = 0.f, a2V1 = 0.f, aUV1 = 0.f;
            float aU2 = 0.f, aV2 = 0.f, a2U2 = 0.f, a2V2 = 0.f, aUV2 = 0.f;
#pragma unroll
            for (int it = 0; it < 11; it++) {
                int c = it * 32 + lane;
                if (c < FEAT) {
                    float4 cf = coef[c];
                    float u = (rSA[c] - cf.x) * cf.y;
                    float v = (rXA[c] - cf.z) * cf.w;
                    aU1 += u; aV1 += v;
                    a2U1 = fmaf(u, u, a2U1);
                    a2V1 = fmaf(v, v, a2V1);
                    aUV1 = fmaf(u, v, aUV1);
                    if (hasB) {
                        float ub = (rSB[c] - cf.x) * cf.y;
                        float vb = (rXB[c] - cf.z) * cf.w;
                        aU2 += ub; aV2 += vb;
                        a2U2 = fmaf(ub, ub, a2U2);
                        a2V2 = fmaf(vb, vb, a2V2);
                        aUV2 = fmaf(ub, vb, aUV2);
                    }
                }
            }
#pragma unroll
            for (int o = 16; o > 0; o >>= 1) {
                aU1  += __shfl_down_sync(0xffffffffu, aU1,  o);
                aV1  += __shfl_down_sync(0xffffffffu, aV1,  o);
                a2U1 += __shfl_down_sync(0xffffffffu, a2U1, o);
                a2V1 += __shfl_down_sync(0xffffffffu, a2V1, o);
                aUV1 += __shfl_down_sync(0xffffffffu, aUV1, o);
                aU2  += __shfl_down_sync(0xffffffffu, aU2,  o);
                aV2  += __shfl_down_sync(0xffffffffu, aV2,  o);
                a2U2 += __shfl_down_sync(0xffffffffu, a2U2, o);
                a2V2 += __shfl_down_sync(0xffffffffu, a2V2, o);
                aUV2 += __shfl_down_sync(0xffffffffu, aUV2, o);
            }
            if (lane == 0) {
                {
                    float muU = aU1 * (1.0f / FEAT), muV = aV1 * (1.0f / FEAT);
                    float sgU = sqrtf(fmaxf(a2U1 - (float)FEAT * muU * muU, 0.f));
                    float sgV = sqrtf(fmaxf(a2V1 - (float)FEAT * muV * muV, 0.f));
                    float dot = aUV1 - (float)FEAT * muU * muV;
                    acc += dot / ((sgU + EPSF) * (sgV + EPSF));
                }
                if (hasB) {
                    float muU = aU2 * (1.0f / FEAT), muV = aV2 * (1.0f / FEAT);
                    float sgU = sqrtf(fmaxf(a2U2 - (float)FEAT * muU * muU, 0.f));
                    float sgV = sqrtf(fmaxf(a2V2 - (float)FEAT * muV * muV, 0.f));
                    float dot = aUV2 - (float)FEAT * muU * muV;
                    acc += dot / ((sgU + EPSF) * (sgV + EPSF));
                }
            }
        }
    }

    if (lane == 0) red[warp] = acc;
    __syncthreads();
    if (tid == 0) {
        float tot = 0.f;
#pragma unroll
        for (int i = 0; i < 16; i++) tot += red[i];
        atomicAdd(&out[b], tot * (1.0f / ((float)FL * (float)NFR)));
    }
}

__global__ void zero_out(float* out, int n)
{
    int i = blockIdx.x * blockDim.x + threadIdx.x;
    if (i < n) out[i] = 0.f;
}

extern "C" void kernel_launch(void* const* d_in, const int* in_sizes, int n_in,
                              void* d_out, int out_size)
{
    const float* s  = (const float*)d_in[0];
    const float* x  = (const float*)d_in[1];
    const float* w0 = (const float*)d_in[2];
    const float* b0 = (const float*)d_in[3];
    const float* w1 = (const float*)d_in[4];
    const float* b1 = (const float*)d_in[5];
    const float* w2 = (const float*)d_in[6];
    const float* b2 = (const float*)d_in[7];
    float* out = (float*)d_out;

    cudaMemcpyToSymbolAsync(CW0, w0, 9 * 1  * K_ * sizeof(float), 0, cudaMemcpyDeviceToDevice, 0);
    cudaMemcpyToSymbolAsync(CB0, b0, K_ * sizeof(float),          0, cudaMemcpyDeviceToDevice, 0);
    cudaMemcpyToSymbolAsync(CW1, w1, 9 * K_ * K_ * sizeof(float), 0, cudaMemcpyDeviceToDevice, 0);
    cudaMemcpyToSymbolAsync(CB1, b1, K_ * sizeof(float),          0, cudaMemcpyDeviceToDevice, 0);
    cudaMemcpyToSymbolAsync(CW2, w2, 9 * K_ * K_ * sizeof(float), 0, cudaMemcpyDeviceToDevice, 0);
    cudaMemcpyToSymbolAsync(CB2, b2, K_ * sizeof(float),          0, cudaMemcpyDeviceToDevice, 0);

    zero_out<<<1, 32>>>(out, out_size);

    const int smem1  = (TB + 2) * (F_ + 2) * 1  * (int)sizeof(float);  //  2432 B
    const int smem20 = (TB + 2) * (F_ + 2) * 21 * (int)sizeof(float);  // 51072 B
    const int smemC  = (2 * ROWS_ST * FEAT) * (int)sizeof(float)
                     + FEAT * (int)sizeof(float4);                     // 103360 B

    cudaFuncSetAttribute(conv_kernel<K_, false, 0, 1, 1>,
                         cudaFuncAttributeMaxDynamicSharedMemorySize, smem20);
    cudaFuncSetAttribute(conv_kernel<K_, false, 1, 0, 2>,
                         cudaFuncAttributeMaxDynamicSharedMemorySize, smem20);
    cudaFuncSetAttribute(corr_kernel,
                         cudaFuncAttributeMaxDynamicSharedMemorySize, smemC);

    dim3 cgrid(NTBLK, 2 * B_);   // 18 x 32 = 576 CTAs
    conv_kernel<1,  true,  0, 0, 0><<<cgrid, 256, smem1 >>>(s, x);             // -> bufA
    conv_kernel<K_, false, 0, 1, 1><<<cgrid, 256, smem20>>>(nullptr, nullptr); // A -> B
    conv_kernel<K_, false, 1, 0, 2><<<cgrid, 256, smem20>>>(nullptr, nullptr); // B -> A

    dim3 ggrid(NGRP, B_);        // 69 x 16 = 1104 CTAs
    corr_kernel<<<ggrid, 512, smemC>>>(out);
}

// round 16
// speedup vs baseline: 1.2209x; 1.1896x over previous
#include <cuda_runtime.h>
#include <math.h>

#define B_   16
#define T_   512
#define F_   17
#define K_   20
#define FEAT (F_*K_)        // 340
#define FL   30
#define NFR  (T_ - FL + 1)  // 483
#define GF   7              // frames per corr CTA (483 = 69*7 exactly)
#define NGRP (NFR / GF)     // 69
#define ROWS_ST (FL + GF - 1)  // 36 staged rows
#define TB   30
#define NTBLK ((T_ + TB - 1) / TB)   // 18
#define EPSF 1e-12f

// Scratch: ping-pong activation buffers for both towers stacked as 32 "batches".
__device__ float g_bufA[2 * B_ * T_ * F_ * K_];
__device__ float g_bufB[2 * B_ * T_ * F_ * K_];

// Weights/biases in constant memory (warp-uniform -> LDC port, no L1TEX).
__constant__ __align__(16) float CW0[9 * 1  * K_];
__constant__ __align__(16) float CW1[9 * K_ * K_];
__constant__ __align__(16) float CW2[9 * K_ * K_];
__constant__ float CB0[K_];
__constant__ float CB1[K_];
__constant__ float CB2[K_];

// ---------------------------------------------------------------------------
// Layer 0 conv (CIN=1). Proven structure; float4 stores.
// ---------------------------------------------------------------------------
__global__ void __launch_bounds__(256) conv1_kernel(
    const float* __restrict__ in0, const float* __restrict__ in1)
{
    extern __shared__ float tile[];   // (TB+2)*(F_+2)

    const int tid = threadIdx.x;
    const int t0  = blockIdx.x * TB;
    const int bb  = blockIdx.y;

    const float* src = (bb < B_) ? (in0 + (size_t)bb * T_ * F_)
                                 : (in1 + (size_t)(bb - B_) * T_ * F_);
    float* dst = g_bufA;

    const int tileN = (TB + 2) * (F_ + 2);
    for (int i = tid; i < tileN; i += 256) {
        int ff = i % (F_ + 2);
        int tt = i / (F_ + 2);
        int t = t0 - 1 + tt;
        int f = ff - 1;
        float v = 0.f;
        if (t >= 0 && t < T_ && f >= 0 && f < F_)
            v = src[(size_t)t * F_ + f];
        tile[i] = v;
    }
    __syncthreads();

    float acc0[K_], acc1[K_];
#pragma unroll
    for (int k = 0; k < K_; k++) { acc0[k] = CB0[k]; acc1[k] = CB0[k]; }

    const bool ok1 = (tid + 256 < TB * F_);
    const int pos0 = tid;
    const int pos1 = ok1 ? (tid + 256) : 0;
    const int lt0 = pos0 / F_, lf0 = pos0 % F_;
    const int lt1 = pos1 / F_, lf1 = pos1 % F_;

#pragma unroll
    for (int dt = 0; dt < 3; dt++) {
#pragma unroll
        for (int df = 0; df < 3; df++) {
            const int wbase = (dt * 3 + df) * K_;
            float i0 = tile[(lt0 + dt) * (F_ + 2) + lf0 + df];
            float i1 = tile[(lt1 + dt) * (F_ + 2) + lf1 + df];
#pragma unroll
            for (int k = 0; k < K_; k++) {
                float wv = CW0[wbase + k];
                acc0[k] = fmaf(i0, wv, acc0[k]);
                acc1[k] = fmaf(i1, wv, acc1[k]);
            }
        }
    }

    if ((t0 + lt0) < T_) {
        float4* o4 = reinterpret_cast<float4*>(
            dst + (((size_t)bb * T_ + t0 + lt0) * F_ + lf0) * K_);
#pragma unroll
        for (int q = 0; q < 5; q++) {
            float4 r;
            r.x = fmaxf(acc0[4*q+0], 0.f);
            r.y = fmaxf(acc0[4*q+1], 0.f);
            r.z = fmaxf(acc0[4*q+2], 0.f);
            r.w = fmaxf(acc0[4*q+3], 0.f);
            o4[q] = r;
        }
    }
    if (ok1 && (t0 + lt1) < T_) {
        float4* o4 = reinterpret_cast<float4*>(
            dst + (((size_t)bb * T_ + t0 + lt1) * F_ + lf1) * K_);
#pragma unroll
        for (int q = 0; q < 5; q++) {
            float4 r;
            r.x = fmaxf(acc1[4*q+0], 0.f);
            r.y = fmaxf(acc1[4*q+1], 0.f);
            r.z = fmaxf(acc1[4*q+2], 0.f);
            r.w = fmaxf(acc1[4*q+3], 0.f);
            o4[q] = r;
        }
    }
}

// ---------------------------------------------------------------------------
// Layers 1/2 conv (CIN=20) — R16: LOOP INTERCHANGE. taps outer (runtime),
// cin INNER fully unrolled. All LDS/LDC addresses become base+immediate,
// killing the ~150 ALU addressing instrs per 360 FFMA seen in R14 profile
// (alu pipe was 16%). Per tap: 20 x (2 LDS[imm] + 5 LDC[imm] + 40 FFMA)
// -> FFMA ~85% of issue slots (was 59%).
// Tile layout/occupancy unchanged: [pos][cin] stride CINP=21, 256 thr,
// TB=30, 4 CTAs/SM.
// ---------------------------------------------------------------------------
template<int SRC, int DST, int LAYER>
__global__ void __launch_bounds__(256) conv20_kernel()
{
    constexpr int CIN  = K_;
    constexpr int CINP = K_ + 1;   // 21

    extern __shared__ float tile[];   // (TB+2)*(F_+2)*CINP

    const int tid = threadIdx.x;
    const int t0  = blockIdx.x * TB;
    const int bb  = blockIdx.y;

    const float* src = ((SRC == 0) ? g_bufA : g_bufB) + (size_t)bb * T_ * F_ * CIN;
    float* dst = ((DST == 0) ? g_bufA : g_bufB);

    const int tileN = (TB + 2) * (F_ + 2) * CIN;
    for (int i = tid; i < tileN; i += 256) {
        int cin  = i % CIN;
        int rest = i / CIN;
        int ff   = rest % (F_ + 2);
        int tt   = rest / (F_ + 2);
        int t = t0 - 1 + tt;
        int f = ff - 1;
        float v = 0.f;
        if (t >= 0 && t < T_ && f >= 0 && f < F_)
            v = src[((size_t)t * F_ + f) * CIN + cin];
        tile[(tt * (F_ + 2) + ff) * CINP + cin] = v;
    }
    __syncthreads();

    float acc0[K_], acc1[K_];
#pragma unroll
    for (int k = 0; k < K_; k++) {
        float bk = (LAYER == 1) ? CB1[k] : CB2[k];
        acc0[k] = bk; acc1[k] = bk;
    }

    const bool ok0 = (tid < TB * F_);
    const bool ok1 = (tid + 256 < TB * F_);
    const int pos0 = ok0 ? tid : 0;
    const int pos1 = ok1 ? (tid + 256) : 0;
    const int b0c = ((pos0 / F_) * (F_ + 2) + (pos0 % F_)) * CINP;
    const int b1c = ((pos1 / F_) * (F_ + 2) + (pos1 % F_)) * CINP;

    const float* cw = (LAYER == 1) ? CW1 : CW2;

    // taps outer (runtime loops), cin inner (fully unrolled, imm offsets)
    for (int dt = 0; dt < 3; dt++) {
        for (int df = 0; df < 3; df++) {
            const int toff = (dt * (F_ + 2) + df) * CINP;
            const float* tp0 = tile + b0c + toff;
            const float* tp1 = tile + b1c + toff;
            const float* wp = cw + (dt * 3 + df) * (CIN * K_);  // uniform base
#pragma unroll
            for (int cin = 0; cin < CIN; cin++) {
                float i0 = tp0[cin];
                float i1 = tp1[cin];
#pragma unroll
                for (int q = 0; q < 5; q++) {
                    float4 wv = reinterpret_cast<const float4*>(wp + cin * K_)[q];
                    acc0[4*q+0] = fmaf(i0, wv.x, acc0[4*q+0]);
                    acc0[4*q+1] = fmaf(i0, wv.y, acc0[4*q+1]);
                    acc0[4*q+2] = fmaf(i0, wv.z, acc0[4*q+2]);
                    acc0[4*q+3] = fmaf(i0, wv.w, acc0[4*q+3]);
                    acc1[4*q+0] = fmaf(i1, wv.x, acc1[4*q+0]);
                    acc1[4*q+1] = fmaf(i1, wv.y, acc1[4*q+1]);
                    acc1[4*q+2] = fmaf(i1, wv.z, acc1[4*q+2]);
                    acc1[4*q+3] = fmaf(i1, wv.w, acc1[4*q+3]);
                }
            }
        }
    }

    if (ok0 && (t0 + pos0 / F_) < T_) {
        int t = t0 + pos0 / F_;
        float4* o4 = reinterpret_cast<float4*>(
            dst + (((size_t)bb * T_ + t) * F_ + pos0 % F_) * K_);
#pragma unroll
        for (int q = 0; q < 5; q++) {
            float4 r;
            r.x = fmaxf(acc0[4*q+0], 0.f);
            r.y = fmaxf(acc0[4*q+1], 0.f);
            r.z = fmaxf(acc0[4*q+2], 0.f);
            r.w = fmaxf(acc0[4*q+3], 0.f);
            o4[q] = r;
        }
    }
    if (ok1 && (t0 + pos1 / F_) < T_) {
        int t = t0 + pos1 / F_;
        float4* o4 = reinterpret_cast<float4*>(
            dst + (((size_t)bb * T_ + t) * F_ + pos1 % F_) * K_);
#pragma unroll
        for (int q = 0; q < 5; q++) {
            float4 r;
            r.x = fmaxf(acc1[4*q+0], 0.f);
            r.y = fmaxf(acc1[4*q+1], 0.f);
            r.z = fmaxf(acc1[4*q+2], 0.f);
            r.w = fmaxf(acc1[4*q+3], 0.f);
            o4[q] = r;
        }
    }
}

// ---------------------------------------------------------------------------
// Grouped per-frame double-normalized cross-correlation — EXACT R14 kernel
// (fp32 throughout; passed at rel_err 4.0e-7). 512 threads, 2 CTAs/SM,
// fresh one-pass stats per frame, warp handles rows (w, w+16) sharing coef.
// ---------------------------------------------------------------------------
__global__ void __launch_bounds__(512, 2) corr_kernel(float* __restrict__ out)
{
    extern __shared__ float sm[];
    float*  rawS = sm;                       // 36*340 fp32
    float*  rawX = sm + ROWS_ST * FEAT;      // 36*340 fp32
    float4* coef = reinterpret_cast<float4*>(sm + 2 * ROWS_ST * FEAT); // 340 float4
    __shared__ float red[16];

    const int grp = blockIdx.x;   // 0..68
    const int b   = blockIdx.y;   // 0..15
    const int tid = threadIdx.x;
    const int fr0 = grp * GF;

    const float* S = g_bufA + ((size_t)b * T_ + fr0) * FEAT;
    const float* X = g_bufA + ((size_t)(b + B_) * T_ + fr0) * FEAT;

    {
        const int n4 = ROWS_ST * FEAT / 4;   // 3060
        const float4* S4 = reinterpret_cast<const float4*>(S);
        const float4* X4 = reinterpret_cast<const float4*>(X);
        float4* rS4 = reinterpret_cast<float4*>(rawS);
        float4* rX4 = reinterpret_cast<float4*>(rawX);
        for (int i = tid; i < n4; i += 512) { rS4[i] = S4[i]; rX4[i] = X4[i]; }
    }
    __syncthreads();

    const int warp = tid >> 5, lane = tid & 31;
    float acc = 0.f;

    const int tA = warp;
    const int tB = warp + 16;
    const bool hasB = (tB < FL);

    for (int j = 0; j < GF; j++) {
        if (j > 0) __syncthreads();

#pragma unroll
        for (int slot = 0; slot < 2; slot++) {
            int task = tid + slot * 512;
            if (task < 2 * FEAT) {
                const bool isS = (task < FEAT);
                const int col = isS ? task : task - FEAT;
                const float* base = isS ? rawS : rawX;
                float s = 0.f, s2 = 0.f;
#pragma unroll
                for (int t = 0; t < FL; t++) {
                    float r = base[(j + t) * FEAT + col];
                    s += r; s2 = fmaf(r, r, s2);
                }
                float mu  = s * (1.0f / FL);
                float var = fmaxf(s2 - (float)FL * mu * mu, 0.f);
                float inv = 1.f / (sqrtf(var) + EPSF);
                if (isS) { coef[col].x = mu; coef[col].y = inv; }
                else     { coef[col].z = mu; coef[col].w = inv; }
            }
        }
        __syncthreads();

        {
            const float* rSA = rawS + (j + tA) * FEAT;
            const float* rXA = rawX + (j + tA) * FEAT;
            const float* rSB = rawS + (j + (hasB ? tB : tA)) * FEAT;
            const float* rXB = rawX + (j + (hasB ? tB : tA)) * FEAT;

            float aU1 = 0.f, aV1 = 0.f, a2U1 = 0.f, a2V1 = 0.f, aUV1 = 0.f;
            float aU2 = 0.f, aV2 = 0.f, a2U2 = 0.f, a2V2 = 0.f, aUV2 = 0.f;
#pragma unroll
            for (int it = 0; it < 11; it++) {
                int c = it * 32 + lane;
                if (c < FEAT) {
                    float4 cf = coef[c];
                    float u = (rSA[c] - cf.x) * cf.y;
                    float v = (rXA[c] - cf.z) * cf.w;
                    aU1 += u; aV1 += v;
                    a2U1 = fmaf(u, u, a2U1);
                    a2V1 = fmaf(v, v, a2V1);
                    aUV1 = fmaf(u, v, aUV1);
                    if (hasB) {
                        float ub = (rSB[c] - cf.x) * cf.y;
                        float vb = (rXB[c] - cf.z) * cf.w;
                        aU2 += ub; aV2 += vb;
                        a2U2 = fmaf(ub, ub, a2U2);
                        a2V2 = fmaf(vb, vb, a2V2);
                        aUV2 = fmaf(ub, vb, aUV2);
                    }
                }
            }
#pragma unroll
            for (int o = 16; o > 0; o >>= 1) {
                aU1  += __shfl_down_sync(0xffffffffu, aU1,  o);
                aV1  += __shfl_down_sync(0xffffffffu, aV1,  o);
                a2U1 += __shfl_down_sync(0xffffffffu, a2U1, o);
                a2V1 += __shfl_down_sync(0xffffffffu, a2V1, o);
                aUV1 += __shfl_down_sync(0xffffffffu, aUV1, o);
                aU2  += __shfl_down_sync(0xffffffffu, aU2,  o);
                aV2  += __shfl_down_sync(0xffffffffu, aV2,  o);
                a2U2 += __shfl_down_sync(0xffffffffu, a2U2, o);
                a2V2 += __shfl_down_sync(0xffffffffu, a2V2, o);
                aUV2 += __shfl_down_sync(0xffffffffu, aUV2, o);
            }
            if (lane == 0) {
                {
                    float muU = aU1 * (1.0f / FEAT), muV = aV1 * (1.0f / FEAT);
                    float sgU = sqrtf(fmaxf(a2U1 - (float)FEAT * muU * muU, 0.f));
                    float sgV = sqrtf(fmaxf(a2V1 - (float)FEAT * muV * muV, 0.f));
                    float dot = aUV1 - (float)FEAT * muU * muV;
                    acc += dot / ((sgU + EPSF) * (sgV + EPSF));
                }
                if (hasB) {
                    float muU = aU2 * (1.0f / FEAT), muV = aV2 * (1.0f / FEAT);
                    float sgU = sqrtf(fmaxf(a2U2 - (float)FEAT * muU * muU, 0.f));
                    float sgV = sqrtf(fmaxf(a2V2 - (float)FEAT * muV * muV, 0.f));
                    float dot = aUV2 - (float)FEAT * muU * muV;
                    acc += dot / ((sgU + EPSF) * (sgV + EPSF));
                }
            }
        }
    }

    if (lane == 0) red[warp] = acc;
    __syncthreads();
    if (tid == 0) {
        float tot = 0.f;
#pragma unroll
        for (int i = 0; i < 16; i++) tot += red[i];
        atomicAdd(&out[b], tot * (1.0f / ((float)FL * (float)NFR)));
    }
}

__global__ void zero_out(float* out, int n)
{
    int i = blockIdx.x * blockDim.x + threadIdx.x;
    if (i < n) out[i] = 0.f;
}

extern "C" void kernel_launch(void* const* d_in, const int* in_sizes, int n_in,
                              void* d_out, int out_size)
{
    const float* s  = (const float*)d_in[0];
    const float* x  = (const float*)d_in[1];
    const float* w0 = (const float*)d_in[2];
    const float* b0 = (const float*)d_in[3];
    const float* w1 = (const float*)d_in[4];
    const float* b1 = (const float*)d_in[5];
    const float* w2 = (const float*)d_in[6];
    const float* b2 = (const float*)d_in[7];
    float* out = (float*)d_out;

    cudaMemcpyToSymbolAsync(CW0, w0, 9 * 1  * K_ * sizeof(float), 0, cudaMemcpyDeviceToDevice, 0);
    cudaMemcpyToSymbolAsync(CB0, b0, K_ * sizeof(float),          0, cudaMemcpyDeviceToDevice, 0);
    cudaMemcpyToSymbolAsync(CW1, w1, 9 * K_ * K_ * sizeof(float), 0, cudaMemcpyDeviceToDevice, 0);
    cudaMemcpyToSymbolAsync(CB1, b1, K_ * sizeof(float),          0, cudaMemcpyDeviceToDevice, 0);
    cudaMemcpyToSymbolAsync(CW2, w2, 9 * K_ * K_ * sizeof(float), 0, cudaMemcpyDeviceToDevice, 0);
    cudaMemcpyToSymbolAsync(CB2, b2, K_ * sizeof(float),          0, cudaMemcpyDeviceToDevice, 0);

    zero_out<<<1, 32>>>(out, out_size);

    const int smem1  = (TB + 2) * (F_ + 2) * 1  * (int)sizeof(float);  //  2432 B
    const int smem20 = (TB + 2) * (F_ + 2) * 21 * (int)sizeof(float);  // 51072 B
    const int smemC  = (2 * ROWS_ST * FEAT) * (int)sizeof(float)
                     + FEAT * (int)sizeof(float4);                     // 103360 B

    cudaFuncSetAttribute(conv20_kernel<0, 1, 1>,
                         cudaFuncAttributeMaxDynamicSharedMemorySize, smem20);
    cudaFuncSetAttribute(conv20_kernel<1, 0, 2>,
                         cudaFuncAttributeMaxDynamicSharedMemorySize, smem20);
    cudaFuncSetAttribute(corr_kernel,
                         cudaFuncAttributeMaxDynamicSharedMemorySize, smemC);

    dim3 cgrid(NTBLK, 2 * B_);   // 18 x 32 = 576 CTAs
    conv1_kernel<<<cgrid, 256, smem1>>>(s, x);          // -> bufA
    conv20_kernel<0, 1, 1><<<cgrid, 256, smem20>>>();   // A -> B
    conv20_kernel<1, 0, 2><<<cgrid, 256, smem20>>>();   // B -> A

    dim3 ggrid(NGRP, B_);        // 69 x 16 = 1104 CTAs
    corr_kernel<<<ggrid, 512, smemC>>>(out);
}